// round 7
// baseline (speedup 1.0000x reference)
#include <cuda_runtime.h>

// VanillaRNN persistent kernel for GB300 (sm_103a) — round 6: dataflow pipeline.
// h_{t+1} = tanh(W_hx * x_t + W_hh @ h_t + b_h), 1024 steps; p = W_ph @ h + b_p.
//
// 128 persistent CTAs = 16 row-groups x 8 batch-groups, 32x32 output tile each.
// NO grid barrier, NO bulk refresh. Per step:
//  - k-loop split into 16 chunks of 32 k-rows; chunk j's data is the tile
//    published by CTA (j, bg) last step.
//  - per-tile flags (release/acquire) + 4-slot smem ring + cp.async prefetch
//    3 chunks ahead -> exchange latency and CTA skew hide behind FFMA work.
//  - thread = 1 row x 4 cols: per 4k = 1 W LDS.128 + 4 h LDS.128 + 16 FMA.

#define HH    512
#define BB    256
#define TT    1024
#define NCLS  10

#define RGN   16
#define BGN   8
#define HR    32
#define BT    32
#define NCTA  (RGN * BGN)
#define NTHR  256

#define W_PAD   516          // W row stride (floats)
#define H_PAD   36           // chunk row stride (floats)
#define NSLOT   4
#define CHUNK_F (32 * H_PAD) // floats per chunk slot

#define SMEM_FLOATS (HR * W_PAD + NSLOT * CHUNK_F + HH + BT)
#define SMEM_BYTES  (SMEM_FLOATS * 4)   // ~86.7 KB

__device__ float    g_h[2][HH][BB];        // double-buffered hidden state
__device__ unsigned g_flag[BGN][RGN][32];  // per-tile step flags, 128B apart

__device__ __forceinline__ void cp16(float* dst_smem, const float* src) {
    unsigned d = (unsigned)__cvta_generic_to_shared(dst_smem);
    asm volatile("cp.async.cg.shared.global [%0], [%1], 16;" :: "r"(d), "l"(src));
}
__device__ __forceinline__ void cp_commit() {
    asm volatile("cp.async.commit_group;" ::: "memory");
}
__device__ __forceinline__ void wait_flag(const unsigned* p, unsigned target) {
    unsigned v;
    do {
        asm volatile("ld.acquire.gpu.u32 %0, [%1];" : "=r"(v) : "l"(p) : "memory");
    } while (v < target);
}

__global__ void __launch_bounds__(NTHR, 1) rnn_persistent(
    const float* __restrict__ x,       // [BB][TT]
    const float* __restrict__ h_init,  // [HH]
    const float* __restrict__ W_hx,    // [HH]
    const float* __restrict__ W_hh,    // [HH][HH]
    const float* __restrict__ b_h,     // [HH]
    const float* __restrict__ W_ph,    // [NCLS][HH]
    const float* __restrict__ b_p,     // [NCLS]
    float* __restrict__ out)           // [BB][NCLS]
{
    extern __shared__ float smem[];
    float* Wr  = smem;                       // [HR][W_PAD]
    float* chk = Wr + HR * W_PAD;            // [NSLOT][32][H_PAD]
    float* his = chk + NSLOT * CHUNK_F;      // [HH]
    float* xs  = his + HH;                   // [BT]

    const int tid   = threadIdx.x;
    const int cta   = blockIdx.x;
    const int rg    = cta >> 3;
    const int bg    = cta & 7;
    const int rbase = rg * HR;
    const int cbase = bg * BT;

    const int r  = tid >> 3;          // 0..31 row in tile
    const int c4 = (tid & 7) << 2;    // 0,4,...,28 col quad

    // ---- resident W_hh slice ----
    for (int i = tid; i < HR * (HH / 4); i += NTHR) {
        int rr = i >> 7, kq = i & 127;
        float4 v = *reinterpret_cast<const float4*>(W_hh + (rbase + rr) * HH + (kq << 2));
        *reinterpret_cast<float4*>(Wr + rr * W_PAD + (kq << 2)) = v;
    }
    for (int k = tid; k < HH; k += NTHR) his[k] = h_init[k];
    if (tid < BT) xs[tid] = x[(cbase + tid) * TT + 0];

    const float bh = b_h[rbase + r];
    const float wx = W_hx[rbase + r];
    const float* wrow = Wr + r * W_PAD;

    __syncthreads();

    // ================= step 0 (from h_init, all cols share one dot) =========
    {
        float dotv = 0.f;
        #pragma unroll 8
        for (int k = 0; k < HH; k += 4) {
            float4 w = *reinterpret_cast<const float4*>(wrow + k);
            float4 h = *reinterpret_cast<const float4*>(his + k);
            dotv = fmaf(w.x, h.x, dotv);
            dotv = fmaf(w.y, h.y, dotv);
            dotv = fmaf(w.z, h.z, dotv);
            dotv = fmaf(w.w, h.w, dotv);
        }
        const float base = dotv + bh;
        float4 o;
        o.x = tanhf(fmaf(wx, xs[c4 + 0], base));
        o.y = tanhf(fmaf(wx, xs[c4 + 1], base));
        o.z = tanhf(fmaf(wx, xs[c4 + 2], base));
        o.w = tanhf(fmaf(wx, xs[c4 + 3], base));
        *reinterpret_cast<float4*>(&g_h[1][rbase + r][cbase + c4]) = o;
        __threadfence();
        __syncthreads();
        if (tid == 0)
            asm volatile("st.release.gpu.u32 [%0], %1;"
                         :: "l"(&g_flag[bg][rg][0]), "r"(1u) : "memory");
    }

    // copy-thread mapping for chunks (same shape as compute mapping)
    const int ck  = tid >> 3;          // k-row within chunk
    const int cc4 = (tid & 7) << 2;    // col quad

    // ================= steps 1 .. TT-1 ======================================
    for (int s = 1; s < TT; ++s) {
        const int buf = s & 1;
        const unsigned tgt = (unsigned)s;

        if (tid < BT) xs[tid] = x[(cbase + tid) * TT + s];

        // prologue: prefetch chunks 0,1,2
        #pragma unroll
        for (int j = 0; j < 3; ++j) {
            wait_flag(&g_flag[bg][j][0], tgt);
            cp16(chk + j * CHUNK_F + ck * H_PAD + cc4,
                 &g_h[buf][(j << 5) + ck][cbase + cc4]);
            cp_commit();
        }

        float4 acc = make_float4(0.f, 0.f, 0.f, 0.f);

        #pragma unroll 1
        for (int j = 0; j < RGN; ++j) {
            if (j < RGN - 2)       asm volatile("cp.async.wait_group 2;" ::: "memory");
            else if (j == RGN - 2) asm volatile("cp.async.wait_group 1;" ::: "memory");
            else                   asm volatile("cp.async.wait_group 0;" ::: "memory");
            __syncthreads();

            const float* ch = chk + (j & (NSLOT - 1)) * CHUNK_F + c4;
            const float* wk = wrow + (j << 5);
            #pragma unroll
            for (int kk = 0; kk < 32; kk += 4) {
                const float4 w  = *reinterpret_cast<const float4*>(wk + kk);
                const float4 h0 = *reinterpret_cast<const float4*>(ch + (kk + 0) * H_PAD);
                const float4 h1 = *reinterpret_cast<const float4*>(ch + (kk + 1) * H_PAD);
                const float4 h2 = *reinterpret_cast<const float4*>(ch + (kk + 2) * H_PAD);
                const float4 h3 = *reinterpret_cast<const float4*>(ch + (kk + 3) * H_PAD);
                acc.x = fmaf(w.x, h0.x, acc.x); acc.y = fmaf(w.x, h0.y, acc.y);
                acc.z = fmaf(w.x, h0.z, acc.z); acc.w = fmaf(w.x, h0.w, acc.w);
                acc.x = fmaf(w.y, h1.x, acc.x); acc.y = fmaf(w.y, h1.y, acc.y);
                acc.z = fmaf(w.y, h1.z, acc.z); acc.w = fmaf(w.y, h1.w, acc.w);
                acc.x = fmaf(w.z, h2.x, acc.x); acc.y = fmaf(w.z, h2.y, acc.y);
                acc.z = fmaf(w.z, h2.z, acc.z); acc.w = fmaf(w.z, h2.w, acc.w);
                acc.x = fmaf(w.w, h3.x, acc.x); acc.y = fmaf(w.w, h3.y, acc.y);
                acc.z = fmaf(w.w, h3.z, acc.z); acc.w = fmaf(w.w, h3.w, acc.w);
            }

            const int jn = j + 3;
            if (jn < RGN) {
                wait_flag(&g_flag[bg][jn][0], tgt);
                cp16(chk + (jn & (NSLOT - 1)) * CHUNK_F + ck * H_PAD + cc4,
                     &g_h[buf][(jn << 5) + ck][cbase + cc4]);
                cp_commit();
            }
        }

        float4 o;
        o.x = tanhf(fmaf(wx, xs[c4 + 0], acc.x + bh));
        o.y = tanhf(fmaf(wx, xs[c4 + 1], acc.y + bh));
        o.z = tanhf(fmaf(wx, xs[c4 + 2], acc.z + bh));
        o.w = tanhf(fmaf(wx, xs[c4 + 3], acc.w + bh));
        *reinterpret_cast<float4*>(&g_h[buf ^ 1][rbase + r][cbase + c4]) = o;

        __threadfence();
        __syncthreads();
        if (tid == 0)
            asm volatile("st.release.gpu.u32 [%0], %1;"
                         :: "l"(&g_flag[bg][rg][0]), "r"((unsigned)(s + 1)) : "memory");
    }

    // ================= final projection (row-group 0 CTAs) ==================
    // final h is in g_h[0] (step 1023 wrote buf 0). Wait for all row groups.
    if (rg == 0) {
        if (tid < RGN) wait_flag(&g_flag[bg][tid][0], (unsigned)TT);
        __syncthreads();

        // load h columns transposed into Wr region: hsT[c][k], stride W_PAD
        float* hsT = Wr;
        for (int i = tid; i < HH * (BT / 4); i += NTHR) {
            int k = i >> 3, cq = (i & 7) << 2;
            float4 v = __ldcg(reinterpret_cast<const float4*>(&g_h[0][k][cbase + cq]));
            hsT[(cq + 0) * W_PAD + k] = v.x;
            hsT[(cq + 1) * W_PAD + k] = v.y;
            hsT[(cq + 2) * W_PAD + k] = v.z;
            hsT[(cq + 3) * W_PAD + k] = v.w;
        }
        __syncthreads();

        for (int idx = tid; idx < BT * NCLS; idx += NTHR) {
            int c = idx & 31;
            int n = idx >> 5;
            float accp = b_p[n];
            const float* wrow2 = W_ph + n * HH;
            const float* hc    = hsT + c * W_PAD;
            #pragma unroll 4
            for (int k = 0; k < HH; k += 4) {
                float4 wv = *reinterpret_cast<const float4*>(wrow2 + k);
                accp = fmaf(wv.x, hc[k + 0], accp);
                accp = fmaf(wv.y, hc[k + 1], accp);
                accp = fmaf(wv.z, hc[k + 2], accp);
                accp = fmaf(wv.w, hc[k + 3], accp);
            }
            out[(cbase + c) * NCLS + n] = accp;
        }
    }
}

extern "C" void kernel_launch(void* const* d_in, const int* in_sizes, int n_in,
                              void* d_out, int out_size) {
    const float* x      = (const float*)d_in[0];
    const float* h_init = (const float*)d_in[1];
    const float* W_hx   = (const float*)d_in[2];
    const float* W_hh   = (const float*)d_in[3];
    const float* b_h    = (const float*)d_in[4];
    const float* W_ph   = (const float*)d_in[5];
    const float* b_p    = (const float*)d_in[6];
    float* out = (float*)d_out;

    void* flagp = nullptr;
    cudaGetSymbolAddress(&flagp, g_flag);
    cudaMemsetAsync(flagp, 0, BGN * RGN * 32 * sizeof(unsigned), 0);

    cudaFuncSetAttribute(rnn_persistent,
                         cudaFuncAttributeMaxDynamicSharedMemorySize, SMEM_BYTES);

    rnn_persistent<<<NCTA, NTHR, SMEM_BYTES, 0>>>(x, h_init, W_hx, W_hh, b_h,
                                                  W_ph, b_p, out);
}

// round 9
// speedup vs baseline: 1.9890x; 1.9890x over previous
#include <cuda_runtime.h>

// VanillaRNN persistent kernel for GB300 (sm_103a) — round 8.
// R7 design (point-to-point flags, triple-buffered h, R1 compute core) with the
// refresh-coverage bug fixed: each 32-row chunk is now loaded with 8 passes of
// 4 rows (k = p*4 + lane>>3), not 4 passes of 4 rows skipping half the chunk.

#define HH    512
#define BB    256
#define TT    1024
#define NCLS  10

#define RGN   16
#define BGN   8
#define HR    32
#define BT    32
#define NCTA  (RGN * BGN)
#define NTHR  256

#define W_PAD 516
#define H_PAD 36

#define SMEM_FLOATS (HR * W_PAD + HH * H_PAD + BT)
#define SMEM_BYTES  (SMEM_FLOATS * 4)

__device__ float    g_h[3][HH][BB];        // triple-buffered hidden state
__device__ unsigned g_flag[BGN][RGN][32];  // per-tile publish counters, 128B apart

__device__ __forceinline__ void wait_flag(const unsigned* p, unsigned target) {
    unsigned v;
    do {
        asm volatile("ld.acquire.gpu.u32 %0, [%1];" : "=r"(v) : "l"(p) : "memory");
    } while (v < target);
}

__global__ void __launch_bounds__(NTHR, 1) rnn_persistent(
    const float* __restrict__ x,       // [BB][TT]
    const float* __restrict__ h_init,  // [HH]
    const float* __restrict__ W_hx,    // [HH]
    const float* __restrict__ W_hh,    // [HH][HH]
    const float* __restrict__ b_h,     // [HH]
    const float* __restrict__ W_ph,    // [NCLS][HH]
    const float* __restrict__ b_p,     // [NCLS]
    float* __restrict__ out)           // [BB][NCLS]
{
    extern __shared__ float smem[];
    float* Wr = smem;                  // [HR][W_PAD]
    float* hs = smem + HR * W_PAD;     // [HH][H_PAD]
    float* xs = hs + HH * H_PAD;       // [BT]

    const int tid   = threadIdx.x;
    const int lane  = tid & 31;
    const int wid   = tid >> 5;
    const int cta   = blockIdx.x;
    const int rg    = cta >> 3;
    const int bg    = cta & 7;
    const int rbase = rg * HR;
    const int cbase = bg * BT;

    // ---- resident W_hh slice (32 rows x 512) ----
    for (int i = tid; i < HR * (HH / 4); i += NTHR) {
        int r  = i >> 7;
        int kq = i & 127;
        float4 v = *reinterpret_cast<const float4*>(W_hh + (rbase + r) * HH + (kq << 2));
        *reinterpret_cast<float4*>(Wr + r * W_PAD + (kq << 2)) = v;
    }

    // ---- init hs with h_init broadcast (step 0 reads this directly) ----
    for (int k = tid; k < HH; k += NTHR) {
        float v = h_init[k];
        float* row = hs + k * H_PAD;
        #pragma unroll
        for (int c = 0; c < BT; ++c) row[c] = v;
    }

    // ---- R1 per-thread 2x2 microtile mapping ----
    const int wr = wid >> 1, wc = wid & 1;
    const int rp = lane >> 3, cp = lane & 7;
    const int r0 = ((wr << 2) + rp) << 1;
    const int c0 = ((wc << 3) + cp) << 1;

    const float bh0 = b_h[rbase + r0];
    const float bh1 = b_h[rbase + r0 + 1];
    const float wx0 = W_hx[rbase + r0];
    const float wx1 = W_hx[rbase + r0 + 1];

    const float* w0p = Wr + r0 * W_PAD;
    const float* w1p = w0p + W_PAD;
    const float* hcp = hs + c0;

    // refresh mapping: warp handles 2 chunks; lane covers (k-row, col-quad)
    const int j0 = (rg + 2 * wid)     & 15;
    const int j1 = (rg + 2 * wid + 1) & 15;
    const int lk  = lane >> 3;         // 0..3  (k-row within 4-row pass)
    const int lc4 = (lane & 7) << 2;   // 0,4,...,28

    __syncthreads();

    for (int s = 0; s < TT; ++s) {
        // ---- refresh hs from producer tiles (skip step 0: h_init in hs) ----
        if (s > 0) {
            const int rbuf = s % 3;
            const unsigned tgt = (unsigned)s;
            if (lane == 0)  wait_flag(&g_flag[bg][j0][0], tgt);
            if (lane == 16) wait_flag(&g_flag[bg][j1][0], tgt);
            __syncwarp();
            {
                const float* src = &g_h[rbuf][j0 << 5][cbase];
                float*       dst = hs + (j0 << 5) * H_PAD;
                #pragma unroll
                for (int p = 0; p < 8; ++p) {
                    int k = (p << 2) + lk;            // 8 passes x 4 rows = 32
                    float4 v = __ldcg(reinterpret_cast<const float4*>(
                                   src + k * BB + lc4));
                    *reinterpret_cast<float4*>(dst + k * H_PAD + lc4) = v;
                }
            }
            {
                const float* src = &g_h[rbuf][j1 << 5][cbase];
                float*       dst = hs + (j1 << 5) * H_PAD;
                #pragma unroll
                for (int p = 0; p < 8; ++p) {
                    int k = (p << 2) + lk;
                    float4 v = __ldcg(reinterpret_cast<const float4*>(
                                   src + k * BB + lc4));
                    *reinterpret_cast<float4*>(dst + k * H_PAD + lc4) = v;
                }
            }
        }
        if (tid < BT) xs[tid] = x[(cbase + tid) * TT + s];
        __syncthreads();

        // ---- R1 compute core (unchanged) ----
        const float xc0 = xs[c0], xc1 = xs[c0 + 1];
        float a00 = fmaf(wx0, xc0, bh0);
        float a01 = fmaf(wx0, xc1, bh0);
        float a10 = fmaf(wx1, xc0, bh1);
        float a11 = fmaf(wx1, xc1, bh1);

        #pragma unroll 8
        for (int k = 0; k < HH; k += 4) {
            const float4 wa = *reinterpret_cast<const float4*>(w0p + k);
            const float4 wb = *reinterpret_cast<const float4*>(w1p + k);
            const float2 h0 = *reinterpret_cast<const float2*>(hcp + (k + 0) * H_PAD);
            const float2 h1 = *reinterpret_cast<const float2*>(hcp + (k + 1) * H_PAD);
            const float2 h2 = *reinterpret_cast<const float2*>(hcp + (k + 2) * H_PAD);
            const float2 h3 = *reinterpret_cast<const float2*>(hcp + (k + 3) * H_PAD);
            a00 = fmaf(wa.x, h0.x, a00); a01 = fmaf(wa.x, h0.y, a01);
            a10 = fmaf(wb.x, h0.x, a10); a11 = fmaf(wb.x, h0.y, a11);
            a00 = fmaf(wa.y, h1.x, a00); a01 = fmaf(wa.y, h1.y, a01);
            a10 = fmaf(wb.y, h1.x, a10); a11 = fmaf(wb.y, h1.y, a11);
            a00 = fmaf(wa.z, h2.x, a00); a01 = fmaf(wa.z, h2.y, a01);
            a10 = fmaf(wb.z, h2.x, a10); a11 = fmaf(wb.z, h2.y, a11);
            a00 = fmaf(wa.w, h3.x, a00); a01 = fmaf(wa.w, h3.y, a01);
            a10 = fmaf(wb.w, h3.x, a10); a11 = fmaf(wb.w, h3.y, a11);
        }

        a00 = tanhf(a00); a01 = tanhf(a01);
        a10 = tanhf(a10); a11 = tanhf(a11);

        // ---- publish h_{s+1} into buf (s+1)%3, then release flag ----
        const int wbuf = (s + 1) % 3;
        *reinterpret_cast<float2*>(&g_h[wbuf][rbase + r0    ][cbase + c0]) = make_float2(a00, a01);
        *reinterpret_cast<float2*>(&g_h[wbuf][rbase + r0 + 1][cbase + c0]) = make_float2(a10, a11);

        __threadfence();
        __syncthreads();
        if (tid == 0)
            asm volatile("st.release.gpu.u32 [%0], %1;"
                         :: "l"(&g_flag[bg][rg][0]), "r"((unsigned)(s + 1)) : "memory");
    }

    // ---- final projection (row-group 0 CTAs); h_1024 is in buf 1024%3 == 1 ----
    if (rg == 0) {
        {
            const unsigned tgt = (unsigned)TT;
            if (lane == 0)  wait_flag(&g_flag[bg][j0][0], tgt);
            if (lane == 16) wait_flag(&g_flag[bg][j1][0], tgt);
            __syncwarp();
            const int rbuf = TT % 3;
            {
                const float* src = &g_h[rbuf][j0 << 5][cbase];
                float*       dst = hs + (j0 << 5) * H_PAD;
                #pragma unroll
                for (int p = 0; p < 8; ++p) {
                    int k = (p << 2) + lk;
                    float4 v = __ldcg(reinterpret_cast<const float4*>(src + k * BB + lc4));
                    *reinterpret_cast<float4*>(dst + k * H_PAD + lc4) = v;
                }
            }
            {
                const float* src = &g_h[rbuf][j1 << 5][cbase];
                float*       dst = hs + (j1 << 5) * H_PAD;
                #pragma unroll
                for (int p = 0; p < 8; ++p) {
                    int k = (p << 2) + lk;
                    float4 v = __ldcg(reinterpret_cast<const float4*>(src + k * BB + lc4));
                    *reinterpret_cast<float4*>(dst + k * H_PAD + lc4) = v;
                }
            }
        }
        __syncthreads();

        // reuse W region for W_ph
        float* Wp = Wr;
        for (int i = tid; i < (NCLS * HH) / 4; i += NTHR) {
            float4 v = *reinterpret_cast<const float4*>(W_ph + (i << 2));
            *reinterpret_cast<float4*>(Wp + (i << 2)) = v;
        }
        __syncthreads();

        for (int idx = tid; idx < BT * NCLS; idx += NTHR) {
            int cl = idx / NCLS;
            int n  = idx - cl * NCLS;
            float acc = b_p[n];
            const float* wrow = Wp + n * HH;
            const float* hcol = hs + cl;
            #pragma unroll 8
            for (int k = 0; k < HH; ++k)
                acc = fmaf(wrow[k], hcol[k * H_PAD], acc);
            out[(cbase + cl) * NCLS + n] = acc;
        }
    }
}

extern "C" void kernel_launch(void* const* d_in, const int* in_sizes, int n_in,
                              void* d_out, int out_size) {
    const float* x      = (const float*)d_in[0];
    const float* h_init = (const float*)d_in[1];
    const float* W_hx   = (const float*)d_in[2];
    const float* W_hh   = (const float*)d_in[3];
    const float* b_h    = (const float*)d_in[4];
    const float* W_ph   = (const float*)d_in[5];
    const float* b_p    = (const float*)d_in[6];
    float* out = (float*)d_out;

    void* flagp = nullptr;
    cudaGetSymbolAddress(&flagp, g_flag);
    cudaMemsetAsync(flagp, 0, BGN * RGN * 32 * sizeof(unsigned), 0);

    cudaFuncSetAttribute(rnn_persistent,
                         cudaFuncAttributeMaxDynamicSharedMemorySize, SMEM_BYTES);

    rnn_persistent<<<NCTA, NTHR, SMEM_BYTES, 0>>>(x, h_init, W_hx, W_hh, b_h,
                                                  W_ph, b_p, out);
}

// round 10
// speedup vs baseline: 2.0913x; 1.0514x over previous
#include <cuda_runtime.h>

// VanillaRNN persistent kernel for GB300 (sm_103a) — round 9.
// R8 (best, 8754us) + occupancy doubling via warp-level k-split:
//  - 512 threads / 16 warps per CTA (4 warps per SMSP, was 2).
//  - lanes 0-15 accumulate k = 0..3 (mod 8), lanes 16-31 k = 4..7 (mod 8) for the
//    SAME 2x2 microtile; 4 x shfl_xor(16) + add combine the halves.
//  - k-interleave => lane halves hit disjoint smem bank halves (stride 144 ≡ 16).
//  - refresh: one 32x32 chunk per warp (was two), same flag protocol.
//  - release store replaces threadfence+release (syncthreads orders CTA stores).

#define HH    512
#define BB    256
#define TT    1024
#define NCLS  10

#define RGN   16
#define BGN   8
#define HR    32
#define BT    32
#define NCTA  (RGN * BGN)
#define NTHR  512

#define W_PAD 516
#define H_PAD 36

#define SMEM_FLOATS (HR * W_PAD + HH * H_PAD + BT)
#define SMEM_BYTES  (SMEM_FLOATS * 4)

__device__ float    g_h[3][HH][BB];        // triple-buffered hidden state
__device__ unsigned g_flag[BGN][RGN][32];  // per-tile publish counters, 128B apart

__device__ __forceinline__ void wait_flag(const unsigned* p, unsigned target) {
    unsigned v;
    do {
        asm volatile("ld.acquire.gpu.u32 %0, [%1];" : "=r"(v) : "l"(p) : "memory");
    } while (v < target);
}

__global__ void __launch_bounds__(NTHR, 1) rnn_persistent(
    const float* __restrict__ x,       // [BB][TT]
    const float* __restrict__ h_init,  // [HH]
    const float* __restrict__ W_hx,    // [HH]
    const float* __restrict__ W_hh,    // [HH][HH]
    const float* __restrict__ b_h,     // [HH]
    const float* __restrict__ W_ph,    // [NCLS][HH]
    const float* __restrict__ b_p,     // [NCLS]
    float* __restrict__ out)           // [BB][NCLS]
{
    extern __shared__ float smem[];
    float* Wr = smem;                  // [HR][W_PAD]
    float* hs = smem + HR * W_PAD;     // [HH][H_PAD]
    float* xs = hs + HH * H_PAD;       // [BT]

    const int tid   = threadIdx.x;
    const int lane  = tid & 31;
    const int wid   = tid >> 5;        // 0..15
    const int cta   = blockIdx.x;
    const int rg    = cta >> 3;
    const int bg    = cta & 7;
    const int rbase = rg * HR;
    const int cbase = bg * BT;

    // ---- resident W_hh slice (32 rows x 512) ----
    for (int i = tid; i < HR * (HH / 4); i += NTHR) {
        int r  = i >> 7;
        int kq = i & 127;
        float4 v = *reinterpret_cast<const float4*>(W_hh + (rbase + r) * HH + (kq << 2));
        *reinterpret_cast<float4*>(Wr + r * W_PAD + (kq << 2)) = v;
    }

    // ---- init hs with h_init broadcast (step 0 reads this directly) ----
    for (int k = tid; k < HH; k += NTHR) {
        float v = h_init[k];
        float* row = hs + k * H_PAD;
        #pragma unroll
        for (int c = 0; c < BT; ++c) row[c] = v;
    }

    // ---- microtile mapping: 16 warps, warp = 4 rows x 16 cols ----
    const int wr  = wid >> 1;          // 0..7  -> rows 4*wr .. 4*wr+3
    const int wc  = wid & 1;           // 0..1  -> cols 16*wc .. +15
    const int pos = lane & 15;
    const int kh  = lane >> 4;         // k-half: 0 -> k%8 in 0..3, 1 -> 4..7
    const int rp  = pos >> 3;          // 0..1
    const int cp  = pos & 7;           // 0..7
    const int r0  = (wr << 2) + (rp << 1);   // rows r0, r0+1
    const int c0  = (wc << 4) + (cp << 1);   // cols c0, c0+1

    const float bh0 = b_h[rbase + r0];
    const float bh1 = b_h[rbase + r0 + 1];
    const float wx0 = W_hx[rbase + r0];
    const float wx1 = W_hx[rbase + r0 + 1];

    const float* w0p = Wr + r0 * W_PAD + (kh << 2);
    const float* w1p = w0p + W_PAD;
    const float* hcp = hs + (kh << 2) * H_PAD + c0;

    // refresh mapping: warp wid handles chunk (rg + wid) & 15
    const int j0  = (rg + wid) & 15;
    const int lk  = lane >> 3;         // 0..3
    const int lc4 = (lane & 7) << 2;   // 0,4,...,28

    __syncthreads();

    for (int s = 0; s < TT; ++s) {
        // ---- refresh hs from producer tiles (skip step 0) ----
        if (s > 0) {
            const int rbuf = s % 3;
            if (lane == 0) wait_flag(&g_flag[bg][j0][0], (unsigned)s);
            __syncwarp();
            const float* src = &g_h[rbuf][j0 << 5][cbase];
            float*       dst = hs + (j0 << 5) * H_PAD;
            #pragma unroll
            for (int p = 0; p < 8; ++p) {
                int k = (p << 2) + lk;
                float4 v = __ldcg(reinterpret_cast<const float4*>(src + k * BB + lc4));
                *reinterpret_cast<float4*>(dst + k * H_PAD + lc4) = v;
            }
        }
        if (tid < BT) xs[tid] = x[(cbase + tid) * TT + s];
        __syncthreads();

        // ---- half-k dot products: 64 chunks of 4 k-rows (stride 8) ----
        float a00 = 0.f, a01 = 0.f, a10 = 0.f, a11 = 0.f;

        #pragma unroll 8
        for (int i = 0; i < 64; ++i) {
            const float4 wa = *reinterpret_cast<const float4*>(w0p + (i << 3));
            const float4 wb = *reinterpret_cast<const float4*>(w1p + (i << 3));
            const float* hb = hcp + (i << 3) * H_PAD;
            const float2 h0 = *reinterpret_cast<const float2*>(hb + 0 * H_PAD);
            const float2 h1 = *reinterpret_cast<const float2*>(hb + 1 * H_PAD);
            const float2 h2 = *reinterpret_cast<const float2*>(hb + 2 * H_PAD);
            const float2 h3 = *reinterpret_cast<const float2*>(hb + 3 * H_PAD);
            a00 = fmaf(wa.x, h0.x, a00); a01 = fmaf(wa.x, h0.y, a01);
            a10 = fmaf(wb.x, h0.x, a10); a11 = fmaf(wb.x, h0.y, a11);
            a00 = fmaf(wa.y, h1.x, a00); a01 = fmaf(wa.y, h1.y, a01);
            a10 = fmaf(wb.y, h1.x, a10); a11 = fmaf(wb.y, h1.y, a11);
            a00 = fmaf(wa.z, h2.x, a00); a01 = fmaf(wa.z, h2.y, a01);
            a10 = fmaf(wb.z, h2.x, a10); a11 = fmaf(wb.z, h2.y, a11);
            a00 = fmaf(wa.w, h3.x, a00); a01 = fmaf(wa.w, h3.y, a01);
            a10 = fmaf(wb.w, h3.x, a10); a11 = fmaf(wb.w, h3.y, a11);
        }

        // ---- combine the two k-halves (lane L <-> L^16 share the microtile) ----
        a00 += __shfl_xor_sync(0xffffffffu, a00, 16);
        a01 += __shfl_xor_sync(0xffffffffu, a01, 16);
        a10 += __shfl_xor_sync(0xffffffffu, a10, 16);
        a11 += __shfl_xor_sync(0xffffffffu, a11, 16);

        // ---- finish + publish: lane half kh stores row r0+kh ----
        const float xc0 = xs[c0], xc1 = xs[c0 + 1];
        const int wbuf = (s + 1) % 3;
        if (kh == 0) {
            float v0 = tanhf(a00 + fmaf(wx0, xc0, bh0));
            float v1 = tanhf(a01 + fmaf(wx0, xc1, bh0));
            *reinterpret_cast<float2*>(&g_h[wbuf][rbase + r0][cbase + c0]) =
                make_float2(v0, v1);
        } else {
            float v0 = tanhf(a10 + fmaf(wx1, xc0, bh1));
            float v1 = tanhf(a11 + fmaf(wx1, xc1, bh1));
            *reinterpret_cast<float2*>(&g_h[wbuf][rbase + r0 + 1][cbase + c0]) =
                make_float2(v0, v1);
        }

        __syncthreads();
        if (tid == 0)
            asm volatile("st.release.gpu.u32 [%0], %1;"
                         :: "l"(&g_flag[bg][rg][0]), "r"((unsigned)(s + 1)) : "memory");
    }

    // ---- final projection (row-group 0 CTAs); h_1024 is in buf 1024%3 == 1 ----
    if (rg == 0) {
        {
            if (lane == 0) wait_flag(&g_flag[bg][j0][0], (unsigned)TT);
            __syncwarp();
            const int rbuf = TT % 3;
            const float* src = &g_h[rbuf][j0 << 5][cbase];
            float*       dst = hs + (j0 << 5) * H_PAD;
            #pragma unroll
            for (int p = 0; p < 8; ++p) {
                int k = (p << 2) + lk;
                float4 v = __ldcg(reinterpret_cast<const float4*>(src + k * BB + lc4));
                *reinterpret_cast<float4*>(dst + k * H_PAD + lc4) = v;
            }
        }
        __syncthreads();

        // reuse W region for W_ph
        float* Wp = Wr;
        for (int i = tid; i < (NCLS * HH) / 4; i += NTHR) {
            float4 v = *reinterpret_cast<const float4*>(W_ph + (i << 2));
            *reinterpret_cast<float4*>(Wp + (i << 2)) = v;
        }
        __syncthreads();

        for (int idx = tid; idx < BT * NCLS; idx += NTHR) {
            int cl = idx / NCLS;
            int n  = idx - cl * NCLS;
            float acc = b_p[n];
            const float* wrow = Wp + n * HH;
            const float* hcol = hs + cl;
            #pragma unroll 8
            for (int k = 0; k < HH; ++k)
                acc = fmaf(wrow[k], hcol[k * H_PAD], acc);
            out[(cbase + cl) * NCLS + n] = acc;
        }
    }
}

extern "C" void kernel_launch(void* const* d_in, const int* in_sizes, int n_in,
                              void* d_out, int out_size) {
    const float* x      = (const float*)d_in[0];
    const float* h_init = (const float*)d_in[1];
    const float* W_hx   = (const float*)d_in[2];
    const float* W_hh   = (const float*)d_in[3];
    const float* b_h    = (const float*)d_in[4];
    const float* W_ph   = (const float*)d_in[5];
    const float* b_p    = (const float*)d_in[6];
    float* out = (float*)d_out;

    void* flagp = nullptr;
    cudaGetSymbolAddress(&flagp, g_flag);
    cudaMemsetAsync(flagp, 0, BGN * RGN * 32 * sizeof(unsigned), 0);

    cudaFuncSetAttribute(rnn_persistent,
                         cudaFuncAttributeMaxDynamicSharedMemorySize, SMEM_BYTES);

    rnn_persistent<<<NCTA, NTHR, SMEM_BYTES, 0>>>(x, h_init, W_hx, W_hh, b_h,
                                                  W_ph, b_p, out);
}

// round 11
// speedup vs baseline: 2.5520x; 1.2203x over previous
#include <cuda_runtime.h>

// VanillaRNN persistent kernel for GB300 (sm_103a) — round 10: W in registers.
// h_{t+1} = tanh(W_hx * x_t + W_hh @ h_t + b_h), 1024 steps; p = W_ph @ h + b_p.
//
// 128 persistent CTAs = 16 row-groups x 8 batch-groups, 32x32 tile each.
// Crossbar-relief design (L1 was 69% busy, the true binder):
//  - warp w owns k-slice [32w,32w+32); lane owns row=lane; its 32 W_hh values
//    live in 8 float4 REGISTERS for all 1024 steps -> zero W smem traffic.
//  - h LDS are full-warp broadcasts (all lanes same address): 256 LDS.128 per
//    warp per step, the unique-read minimum.
//  - 16 k-slice partials per output reduced via padded smem + 1 extra sync.
//  - refresh / per-tile flag protocol identical to R10 (proven).

#define HH    512
#define BB    256
#define TT    1024
#define NCLS  10

#define RGN   16
#define BGN   8
#define HR    32
#define BT    32
#define NCTA  (RGN * BGN)
#define NTHR  512

#define H_PAD   36
#define RED_STR 36                       // partial-row stride (floats), 16B-mult

#define SMEM_FLOATS (HH * H_PAD + 16 * 32 * RED_STR + BT)
#define SMEM_BYTES  (SMEM_FLOATS * 4)    // ~141 KB

__device__ float    g_h[3][HH][BB];        // triple-buffered hidden state
__device__ unsigned g_flag[BGN][RGN][32];  // per-tile publish counters, 128B apart

__device__ __forceinline__ void wait_flag(const unsigned* p, unsigned target) {
    unsigned v;
    do {
        asm volatile("ld.acquire.gpu.u32 %0, [%1];" : "=r"(v) : "l"(p) : "memory");
    } while (v < target);
}

__global__ void __launch_bounds__(NTHR, 1) rnn_persistent(
    const float* __restrict__ x,       // [BB][TT]
    const float* __restrict__ h_init,  // [HH]
    const float* __restrict__ W_hx,    // [HH]
    const float* __restrict__ W_hh,    // [HH][HH]
    const float* __restrict__ b_h,     // [HH]
    const float* __restrict__ W_ph,    // [NCLS][HH]
    const float* __restrict__ b_p,     // [NCLS]
    float* __restrict__ out)           // [BB][NCLS]
{
    extern __shared__ float smem[];
    float* hs  = smem;                        // [HH][H_PAD]
    float* red = smem + HH * H_PAD;           // [16][32][RED_STR]
    float* xs  = red + 16 * 32 * RED_STR;     // [BT]

    const int tid   = threadIdx.x;
    const int lane  = tid & 31;
    const int wid   = tid >> 5;        // 0..15 : k-slice
    const int cta   = blockIdx.x;
    const int rg    = cta >> 3;
    const int bg    = cta & 7;
    const int rbase = rg * HR;
    const int cbase = bg * BT;
    const int k0    = wid << 5;

    // ---- W_hh slice for this thread: row=lane, k in [k0,k0+32) -> registers ----
    float4 W4[8];
    {
        const float* wsrc = W_hh + (rbase + lane) * HH + k0;
        #pragma unroll
        for (int j = 0; j < 8; ++j)
            W4[j] = *reinterpret_cast<const float4*>(wsrc + (j << 2));
    }

    // ---- init hs with h_init broadcast (step 0 reads this) ----
    for (int k = tid; k < HH; k += NTHR) {
        float v = h_init[k];
        float* row = hs + k * H_PAD;
        #pragma unroll
        for (int c = 0; c < BT; ++c) row[c] = v;
    }

    // ---- reduce/publish mapping: thread -> (row ro, col pair cp) ----
    const int ro = tid >> 4;            // 0..31
    const int cp = (tid & 15) << 1;     // 0,2,...,30
    const float bh = b_h[rbase + ro];
    const float wx = W_hx[rbase + ro];

    // ---- refresh mapping: warp wid handles chunk (rg+wid)&15 ----
    const int j0  = (rg + wid) & 15;
    const int lk  = lane >> 3;
    const int lc4 = (lane & 7) << 2;

    __syncthreads();

    for (int s = 0; s < TT; ++s) {
        // ---- refresh hs from producer tiles (skip step 0) ----
        if (s > 0) {
            const int rbuf = s % 3;
            if (lane == 0) wait_flag(&g_flag[bg][j0][0], (unsigned)s);
            __syncwarp();
            const float* src = &g_h[rbuf][j0 << 5][cbase];
            float*       dst = hs + (j0 << 5) * H_PAD;
            #pragma unroll
            for (int p = 0; p < 8; ++p) {
                int k = (p << 2) + lk;
                float4 v = __ldcg(reinterpret_cast<const float4*>(src + k * BB + lc4));
                *reinterpret_cast<float4*>(dst + k * H_PAD + lc4) = v;
            }
        }
        if (tid < BT) xs[tid] = x[(cbase + tid) * TT + s];
        __syncthreads();

        // ---- partial GEMV: row=lane, 32 k's, all 32 cols; h loads broadcast ----
        float4 A[8];
        #pragma unroll
        for (int q = 0; q < 8; ++q) A[q] = make_float4(0.f, 0.f, 0.f, 0.f);

        const float* hb = hs + k0 * H_PAD;
        #pragma unroll
        for (int kc = 0; kc < 8; ++kc) {
            const float4 w  = W4[kc];
            const float* hr = hb + (kc << 2) * H_PAD;
            #pragma unroll
            for (int q = 0; q < 8; ++q) {
                const float4 ha = *reinterpret_cast<const float4*>(hr + (q << 2));
                A[q].x = fmaf(w.x, ha.x, A[q].x); A[q].y = fmaf(w.x, ha.y, A[q].y);
                A[q].z = fmaf(w.x, ha.z, A[q].z); A[q].w = fmaf(w.x, ha.w, A[q].w);
            }
            #pragma unroll
            for (int q = 0; q < 8; ++q) {
                const float4 ha = *reinterpret_cast<const float4*>(hr + H_PAD + (q << 2));
                A[q].x = fmaf(w.y, ha.x, A[q].x); A[q].y = fmaf(w.y, ha.y, A[q].y);
                A[q].z = fmaf(w.y, ha.z, A[q].z); A[q].w = fmaf(w.y, ha.w, A[q].w);
            }
            #pragma unroll
            for (int q = 0; q < 8; ++q) {
                const float4 ha = *reinterpret_cast<const float4*>(hr + 2 * H_PAD + (q << 2));
                A[q].x = fmaf(w.z, ha.x, A[q].x); A[q].y = fmaf(w.z, ha.y, A[q].y);
                A[q].z = fmaf(w.z, ha.z, A[q].z); A[q].w = fmaf(w.z, ha.w, A[q].w);
            }
            #pragma unroll
            for (int q = 0; q < 8; ++q) {
                const float4 ha = *reinterpret_cast<const float4*>(hr + 3 * H_PAD + (q << 2));
                A[q].x = fmaf(w.w, ha.x, A[q].x); A[q].y = fmaf(w.w, ha.y, A[q].y);
                A[q].z = fmaf(w.w, ha.z, A[q].z); A[q].w = fmaf(w.w, ha.w, A[q].w);
            }
        }

        // ---- write partials: red[wid][lane][0..31] ----
        float* myred = red + ((wid << 5) + lane) * RED_STR;
        #pragma unroll
        for (int q = 0; q < 8; ++q)
            *reinterpret_cast<float4*>(myred + (q << 2)) = A[q];
        __syncthreads();

        // ---- reduce 16 k-slice partials, finish, publish ----
        {
            const float* rr = red + ro * RED_STR + cp;
            float s0 = 0.f, s1 = 0.f;
            #pragma unroll
            for (int w = 0; w < 16; ++w) {
                s0 += rr[(w << 5) * RED_STR];
                s1 += rr[(w << 5) * RED_STR + 1];
            }
            float v0 = tanhf(s0 + fmaf(wx, xs[cp],     bh));
            float v1 = tanhf(s1 + fmaf(wx, xs[cp + 1], bh));
            const int wbuf = (s + 1) % 3;
            *reinterpret_cast<float2*>(&g_h[wbuf][rbase + ro][cbase + cp]) =
                make_float2(v0, v1);
        }

        __syncthreads();
        if (tid == 0)
            asm volatile("st.release.gpu.u32 [%0], %1;"
                         :: "l"(&g_flag[bg][rg][0]), "r"((unsigned)(s + 1)) : "memory");
    }

    // ---- final projection (row-group 0 CTAs); h_1024 in buf 1024%3 == 1 ----
    if (rg == 0) {
        {
            if (lane == 0) wait_flag(&g_flag[bg][j0][0], (unsigned)TT);
            __syncwarp();
            const int rbuf = TT % 3;
            const float* src = &g_h[rbuf][j0 << 5][cbase];
            float*       dst = hs + (j0 << 5) * H_PAD;
            #pragma unroll
            for (int p = 0; p < 8; ++p) {
                int k = (p << 2) + lk;
                float4 v = __ldcg(reinterpret_cast<const float4*>(src + k * BB + lc4));
                *reinterpret_cast<float4*>(dst + k * H_PAD + lc4) = v;
            }
        }
        __syncthreads();

        // reuse reduction buffer for W_ph (10*512 floats)
        float* Wp = red;
        for (int i = tid; i < (NCLS * HH) / 4; i += NTHR) {
            float4 v = *reinterpret_cast<const float4*>(W_ph + (i << 2));
            *reinterpret_cast<float4*>(Wp + (i << 2)) = v;
        }
        __syncthreads();

        for (int idx = tid; idx < BT * NCLS; idx += NTHR) {
            int cl = idx / NCLS;
            int n  = idx - cl * NCLS;
            float acc = b_p[n];
            const float* wrow = Wp + n * HH;
            const float* hcol = hs + cl;
            #pragma unroll 8
            for (int k = 0; k < HH; ++k)
                acc = fmaf(wrow[k], hcol[k * H_PAD], acc);
            out[(cbase + cl) * NCLS + n] = acc;
        }
    }
}

extern "C" void kernel_launch(void* const* d_in, const int* in_sizes, int n_in,
                              void* d_out, int out_size) {
    const float* x      = (const float*)d_in[0];
    const float* h_init = (const float*)d_in[1];
    const float* W_hx   = (const float*)d_in[2];
    const float* W_hh   = (const float*)d_in[3];
    const float* b_h    = (const float*)d_in[4];
    const float* W_ph   = (const float*)d_in[5];
    const float* b_p    = (const float*)d_in[6];
    float* out = (float*)d_out;

    void* flagp = nullptr;
    cudaGetSymbolAddress(&flagp, g_flag);
    cudaMemsetAsync(flagp, 0, BGN * RGN * 32 * sizeof(unsigned), 0);

    cudaFuncSetAttribute(rnn_persistent,
                         cudaFuncAttributeMaxDynamicSharedMemorySize, SMEM_BYTES);

    rnn_persistent<<<NCTA, NTHR, SMEM_BYTES, 0>>>(x, h_init, W_hx, W_hh, b_h,
                                                  W_ph, b_p, out);
}